// round 17
// baseline (speedup 1.0000x reference)
#include <cuda_runtime.h>
#include <cuda_fp16.h>
#include <math.h>
#include <stdint.h>

// Problem constants
#define T_TOK 8192
#define HDIM  1024
#define FDIM  3584
#define NEXP  8
#define TOPK  2
#define BM    128
#define ROWS_MAX (T_TOK*TOPK + NEXP*BM)   // 17408
#define OUT_ELEMS (T_TOK*HDIM)

// smem geometry: fp16, 64B rows (32 elems), SW64 swizzle
#define APL    8192                  // 128 rows * 64 B (A plane)
#define BPL    4096                  // 64 rows * 64 B  (B plane)
#define G1_STAGEB (APL + 2*BPL)      // 16384 (A, B1, B3)
#define G2_STAGEB (APL + 1*BPL)      // 12288 (A, B)
#define G1_STAGES 4
#define G2_STAGES 4
#define SW64B(o) ((o) ^ (((o) >> 3) & 0x30))

#define WELEMS ((size_t)NEXP*FDIM*HDIM)   // 29,360,128

// ---------------- device scratch ----------------
__device__ __half g_xh[(size_t)T_TOK*HDIM];
__device__ __half g_hh[(size_t)ROWS_MAX*FDIM];
__device__ int   g_row_token[ROWS_MAX];
__device__ float g_row_weight[ROWS_MAX];
__device__ int   g_counts[NEXP];
__device__ int   g_offsets[NEXP + 1];
__device__ int   g_cursor[NEXP];
__device__ int   g_total_rows;
__device__ int   g_tok_expert[T_TOK * TOPK];
__device__ float g_tok_weight[T_TOK * TOPK];

// ---------------- helpers ----------------
__device__ __forceinline__ uint32_t smem_u32(const void* p) {
    uint32_t a;
    asm("{ .reg .u64 t; cvta.to.shared.u64 t, %1; cvt.u32.u64 %0, t; }" : "=r"(a) : "l"(p));
    return a;
}
__device__ __forceinline__ uint32_t pack2h(float x, float y) {
    __half2 t = __floats2half2_rn(x, y);
    return *(uint32_t*)&t;
}
__device__ __forceinline__ void mma16816(float (&d)[4], const uint32_t (&a)[4],
                                         uint32_t b0, uint32_t b1) {
    asm volatile(
        "mma.sync.aligned.m16n8k16.row.col.f32.f16.f16.f32 "
        "{%0,%1,%2,%3}, {%4,%5,%6,%7}, {%8,%9}, {%0,%1,%2,%3};"
        : "+f"(d[0]), "+f"(d[1]), "+f"(d[2]), "+f"(d[3])
        : "r"(a[0]), "r"(a[1]), "r"(a[2]), "r"(a[3]), "r"(b0), "r"(b1));
}
__device__ __forceinline__ void ldm4(uint32_t addr, uint32_t (&r)[4]) {
    asm volatile("ldmatrix.sync.aligned.m8n8.x4.shared.b16 {%0,%1,%2,%3}, [%4];"
                 : "=r"(r[0]), "=r"(r[1]), "=r"(r[2]), "=r"(r[3]) : "r"(addr));
}
__device__ __forceinline__ void cpa16(uint32_t dst, const void* src, int sz) {
    asm volatile("cp.async.cg.shared.global [%0], [%1], 16, %2;"
                 :: "r"(dst), "l"(src), "r"(sz) : "memory");
}
#define CP_COMMIT() asm volatile("cp.async.commit_group;" ::: "memory")
#define CP_WAIT2()  asm volatile("cp.async.wait_group 2;" ::: "memory")
#define CP_WAIT0()  asm volatile("cp.async.wait_group 0;" ::: "memory")

// ---------------- 0) init ----------------
__global__ void init_kernel(float* __restrict__ out) {
    int i = blockIdx.x * blockDim.x + threadIdx.x;
    if (i < OUT_ELEMS) out[i] = 0.0f;
    if (i < ROWS_MAX) { g_row_token[i] = -1; g_row_weight[i] = 0.0f; }
    if (i < NEXP) g_counts[i] = 0;
}

// ---------------- 1) router (+ fused x -> fp16 conversion) ----------------
__global__ void router_kernel(const float* __restrict__ x,
                              const float* __restrict__ gate_w,
                              float* __restrict__ logits_out) {
    __shared__ float s_gate[NEXP * HDIM];
    for (int i = threadIdx.x; i < NEXP * HDIM; i += blockDim.x)
        s_gate[i] = gate_w[i];
    __syncthreads();

    int warp = threadIdx.x >> 5, lane = threadIdx.x & 31;
    int t = blockIdx.x * (blockDim.x >> 5) + warp;
    if (t >= T_TOK) return;

    float acc[NEXP];
#pragma unroll
    for (int e = 0; e < NEXP; e++) acc[e] = 0.0f;
    const float* xr = x + (size_t)t * HDIM;
    __half* xo = g_xh + (size_t)t * HDIM;
    for (int j = lane; j < HDIM; j += 32) {
        float xv = xr[j];
        xo[j] = __float2half_rn(xv);
#pragma unroll
        for (int e = 0; e < NEXP; e++) acc[e] += xv * s_gate[e * HDIM + j];
    }
#pragma unroll
    for (int e = 0; e < NEXP; e++) {
#pragma unroll
        for (int o = 16; o > 0; o >>= 1)
            acc[e] += __shfl_xor_sync(0xffffffffu, acc[e], o);
    }
    if (lane == 0) {
        float mx = acc[0];
#pragma unroll
        for (int e = 1; e < NEXP; e++) mx = fmaxf(mx, acc[e]);
        float p[NEXP], s = 0.0f;
#pragma unroll
        for (int e = 0; e < NEXP; e++) { p[e] = expf(acc[e] - mx); s += p[e]; }
        float inv = 1.0f / s;
#pragma unroll
        for (int e = 0; e < NEXP; e++) p[e] *= inv;
        int i0 = 0;
#pragma unroll
        for (int e = 1; e < NEXP; e++) if (p[e] > p[i0]) i0 = e;
        int i1 = (i0 == 0) ? 1 : 0;
#pragma unroll
        for (int e = 0; e < NEXP; e++) if (e != i0 && p[e] > p[i1]) i1 = e;
        float w0 = p[i0], w1 = p[i1], ws = 1.0f / (w0 + w1);
        w0 *= ws; w1 *= ws;
#pragma unroll
        for (int e = 0; e < NEXP; e++) logits_out[(size_t)t * NEXP + e] = acc[e];
        g_tok_expert[t * 2 + 0] = i0; g_tok_expert[t * 2 + 1] = i1;
        g_tok_weight[t * 2 + 0] = w0; g_tok_weight[t * 2 + 1] = w1;
        atomicAdd(&g_counts[i0], 1);
        atomicAdd(&g_counts[i1], 1);
    }
}

// ---------------- 2) scan ----------------
__global__ void scan_kernel() {
    int total = 0;
    for (int e = 0; e < NEXP; e++) {
        g_offsets[e] = total;
        g_cursor[e]  = total;
        int padded = ((g_counts[e] + BM - 1) / BM) * BM;
        total += padded;
    }
    g_offsets[NEXP] = total;
    g_total_rows = total;
}

// ---------------- 3) scatter ----------------
__global__ void scatter_kernel() {
    int t = blockIdx.x * blockDim.x + threadIdx.x;
    if (t >= T_TOK) return;
#pragma unroll
    for (int s = 0; s < TOPK; s++) {
        int e = g_tok_expert[t * 2 + s];
        int p = atomicAdd(&g_cursor[e], 1);
        g_row_token[p]  = t;
        g_row_weight[p] = g_tok_weight[t * 2 + s];
    }
}

// ---------------- 4) GEMM1: fp16 mma, A cp.async, B fp32->fp16 in-loader -------
__global__ __launch_bounds__(128, 2)
void gemm1_mma(const float* __restrict__ w1, const float* __restrict__ w3) {
    int row0 = blockIdx.x * BM;
    if (row0 >= g_total_rows) return;
    int n0 = blockIdx.y * 64;

    int e = 0;
#pragma unroll
    for (int i = 0; i < NEXP; i++) if (row0 >= g_offsets[i + 1]) e = i + 1;

    extern __shared__ char smem[];
    uint32_t sb = smem_u32(smem);
    int tid = threadIdx.x, wid = tid >> 5, lane = tid & 31;
    int wm = wid & 1, wn = wid >> 1;

    const float* w1e = w1 + (size_t)e * FDIM * HDIM;
    const float* w3e = w3 + (size_t)e * FDIM * HDIM;

    int tokc[4];
#pragma unroll
    for (int i = 0; i < 4; i++) tokc[i] = g_row_token[row0 + ((tid + i * 128) >> 2)];

    float acc1[4][4][4], acc3[4][4][4];
#pragma unroll
    for (int m = 0; m < 4; m++)
#pragma unroll
        for (int j = 0; j < 4; j++)
#pragma unroll
            for (int q = 0; q < 4; q++) { acc1[m][j][q] = 0.0f; acc3[m][j][q] = 0.0f; }

    const int NC = HDIM / 32;

    int r8 = lane & 7;
    uint32_t rowA_l = (uint32_t)(((lane >> 3) & 1) * 8 + r8);
    uint32_t kAb    = (uint32_t)(((lane >> 4) & 1) * 16);
    uint32_t nB_l   = (uint32_t)(((lane >> 4) & 1) * 8 + r8);
    uint32_t kBb    = (uint32_t)(((lane >> 3) & 1) * 16);

    // B staging regs: 8 units of 4 floats (2 planes x 64 rows x 8 col4-units)
    float4 regB[8];

    auto cpaA = [&](int cn) {
        int k0 = cn * 32;
        uint32_t st = sb + (cn % G1_STAGES) * G1_STAGEB;
#pragma unroll
        for (int i = 0; i < 4; i++) {
            int idx2 = tid + i * 128;
            int c16 = idx2 & 3, row = idx2 >> 2;
            uint32_t dst = st + SW64B((uint32_t)(row * 64 + c16 * 16));
            int t = tokc[i];
            const __half* src = g_xh + ((size_t)(t < 0 ? 0 : t) * HDIM + k0 + c16 * 8);
            cpa16(dst, src, t < 0 ? 0 : 16);
        }
        CP_COMMIT();
    };
    auto ldgB = [&](int cn) {
        int k0 = cn * 32;
#pragma unroll
        for (int i = 0; i < 8; i++) {
            int idx2 = tid + i * 128;
            int c8 = idx2 & 7, plane = (idx2 >> 3) & 1, row = idx2 >> 4;
            const float* src = (plane ? w3e : w1e)
                + ((size_t)(n0 + row) * HDIM + k0 + c8 * 4);
            regB[i] = *(const float4*)src;
        }
    };
    auto stsB = [&](int cn) {
        uint32_t st = sb + (cn % G1_STAGES) * G1_STAGEB + APL;
#pragma unroll
        for (int i = 0; i < 8; i++) {
            int idx2 = tid + i * 128;
            int c8 = idx2 & 7, plane = (idx2 >> 3) & 1, row = idx2 >> 4;
            uint32_t dst = st + plane * BPL + SW64B((uint32_t)(row * 64 + c8 * 8));
            uint2 v = make_uint2(pack2h(regB[i].x, regB[i].y), pack2h(regB[i].z, regB[i].w));
            *(uint2*)(smem + (dst - sb)) = v;
        }
    };

    // prologue
    ldgB(0); stsB(0);
    cpaA(0); cpaA(1); cpaA(2);
    ldgB(1);

    for (int c = 0; c < NC; c++) {
        if (c + 3 < NC) { CP_WAIT2(); } else { CP_WAIT0(); }
        __syncthreads();
        if (c + 1 < NC) stsB(c + 1);
        if (c + 2 < NC) ldgB(c + 2);
        if (c + 3 < NC) cpaA(c + 3);
        uint32_t st = sb + (c % G1_STAGES) * G1_STAGEB;
#pragma unroll
        for (int kk = 0; kk < 2; kk++) {
            uint32_t A[4][4];
#pragma unroll
            for (int mb = 0; mb < 4; mb++) {
                uint32_t off = SW64B((uint32_t)((wm * 64 + mb * 16 + rowA_l) * 64 + kk * 32 + kAb));
                ldm4(st + off, A[mb]);
            }
#pragma unroll
            for (int jp = 0; jp < 2; jp++) {
                uint32_t boff = SW64B((uint32_t)((wn * 32 + jp * 16 + nB_l) * 64 + kk * 32 + kBb));
                uint32_t bb = st + APL + boff;
                uint32_t B1[4], B3[4];
                ldm4(bb,       B1);
                ldm4(bb + BPL, B3);
                int j0 = jp * 2;
#pragma unroll
                for (int mb = 0; mb < 4; mb++) {
                    mma16816(acc1[mb][j0],   A[mb], B1[0], B1[1]);
                    mma16816(acc1[mb][j0+1], A[mb], B1[2], B1[3]);
                    mma16816(acc3[mb][j0],   A[mb], B3[0], B3[1]);
                    mma16816(acc3[mb][j0+1], A[mb], B3[2], B3[3]);
                }
            }
        }
    }

    // epilogue: h = silu(g)*u -> fp16
#pragma unroll
    for (int mb = 0; mb < 4; mb++) {
        int rA = row0 + wm * 64 + mb * 16 + (lane >> 2);
        int rB = rA + 8;
#pragma unroll
        for (int j = 0; j < 4; j++) {
            int col = n0 + wn * 32 + j * 8 + (lane & 3) * 2;
            float g0 = acc1[mb][j][0], g1 = acc1[mb][j][1];
            float g2 = acc1[mb][j][2], g3 = acc1[mb][j][3];
            float u0 = acc3[mb][j][0], u1 = acc3[mb][j][1];
            float u2 = acc3[mb][j][2], u3 = acc3[mb][j][3];
            float h0 = g0 / (1.0f + __expf(-g0)) * u0;
            float h1 = g1 / (1.0f + __expf(-g1)) * u1;
            float h2 = g2 / (1.0f + __expf(-g2)) * u2;
            float h3 = g3 / (1.0f + __expf(-g3)) * u3;
            *(uint32_t*)(g_hh + (size_t)rA * FDIM + col) = pack2h(h0, h1);
            *(uint32_t*)(g_hh + (size_t)rB * FDIM + col) = pack2h(h2, h3);
        }
    }
}

// ---------------- 5) GEMM2: fp16 mma, A cp.async, B fp32->fp16 in-loader -------
__global__ __launch_bounds__(128, 2)
void gemm2_mma(const float* __restrict__ w2, float* __restrict__ out) {
    int row0 = blockIdx.x * BM;
    if (row0 >= g_total_rows) return;
    int n0 = blockIdx.y * 64;

    int e = 0;
#pragma unroll
    for (int i = 0; i < NEXP; i++) if (row0 >= g_offsets[i + 1]) e = i + 1;

    extern __shared__ char smem[];
    uint32_t sb = smem_u32(smem);
    int tid = threadIdx.x, wid = tid >> 5, lane = tid & 31;
    int wm = wid & 1, wn = wid >> 1;

    const float* w2e = w2 + (size_t)e * HDIM * FDIM;

    float acc[4][4][4];
#pragma unroll
    for (int m = 0; m < 4; m++)
#pragma unroll
        for (int j = 0; j < 4; j++)
#pragma unroll
            for (int q = 0; q < 4; q++) acc[m][j][q] = 0.0f;

    const int NC = FDIM / 32;

    int r8 = lane & 7;
    uint32_t rowA_l = (uint32_t)(((lane >> 3) & 1) * 8 + r8);
    uint32_t kAb    = (uint32_t)(((lane >> 4) & 1) * 16);
    uint32_t nB_l   = (uint32_t)(((lane >> 4) & 1) * 8 + r8);
    uint32_t kBb    = (uint32_t)(((lane >> 3) & 1) * 16);

    float4 regB[4];   // 64 rows x 8 col4-units = 512 units / 128 thr

    auto cpaA = [&](int cn) {
        int k0 = cn * 32;
        uint32_t st = sb + (cn % G2_STAGES) * G2_STAGEB;
#pragma unroll
        for (int i = 0; i < 4; i++) {
            int idx2 = tid + i * 128;
            int c16 = idx2 & 3, row = idx2 >> 2;
            uint32_t dst = st + SW64B((uint32_t)(row * 64 + c16 * 16));
            cpa16(dst, g_hh + ((size_t)(row0 + row) * FDIM + k0 + c16 * 8), 16);
        }
        CP_COMMIT();
    };
    auto ldgB = [&](int cn) {
        int k0 = cn * 32;
#pragma unroll
        for (int i = 0; i < 4; i++) {
            int idx2 = tid + i * 128;
            int c8 = idx2 & 7, row = idx2 >> 3;
            regB[i] = *(const float4*)(w2e + ((size_t)(n0 + row) * FDIM + k0 + c8 * 4));
        }
    };
    auto stsB = [&](int cn) {
        uint32_t st = sb + (cn % G2_STAGES) * G2_STAGEB + APL;
#pragma unroll
        for (int i = 0; i < 4; i++) {
            int idx2 = tid + i * 128;
            int c8 = idx2 & 7, row = idx2 >> 3;
            uint32_t dst = st + SW64B((uint32_t)(row * 64 + c8 * 8));
            uint2 v = make_uint2(pack2h(regB[i].x, regB[i].y), pack2h(regB[i].z, regB[i].w));
            *(uint2*)(smem + (dst - sb)) = v;
        }
    };

    ldgB(0); stsB(0);
    cpaA(0); cpaA(1); cpaA(2);
    ldgB(1);

    for (int c = 0; c < NC; c++) {
        if (c + 3 < NC) { CP_WAIT2(); } else { CP_WAIT0(); }
        __syncthreads();
        if (c + 1 < NC) stsB(c + 1);
        if (c + 2 < NC) ldgB(c + 2);
        if (c + 3 < NC) cpaA(c + 3);
        uint32_t st = sb + (c % G2_STAGES) * G2_STAGEB;
#pragma unroll
        for (int kk = 0; kk < 2; kk++) {
            uint32_t A[4][4];
#pragma unroll
            for (int mb = 0; mb < 4; mb++) {
                uint32_t off = SW64B((uint32_t)((wm * 64 + mb * 16 + rowA_l) * 64 + kk * 32 + kAb));
                ldm4(st + off, A[mb]);
            }
#pragma unroll
            for (int jp = 0; jp < 2; jp++) {
                uint32_t boff = SW64B((uint32_t)((wn * 32 + jp * 16 + nB_l) * 64 + kk * 32 + kBb));
                uint32_t B[4];
                ldm4(st + APL + boff, B);
                int j0 = jp * 2;
#pragma unroll
                for (int mb = 0; mb < 4; mb++) {
                    mma16816(acc[mb][j0],   A[mb], B[0], B[1]);
                    mma16816(acc[mb][j0+1], A[mb], B[2], B[3]);
                }
            }
        }
    }

    // epilogue: weighted atomicAdd
#pragma unroll
    for (int mb = 0; mb < 4; mb++) {
        int rA = row0 + wm * 64 + mb * 16 + (lane >> 2);
        int rB = rA + 8;
        int tA = g_row_token[rA], tB = g_row_token[rB];
        float wA = g_row_weight[rA], wB = g_row_weight[rB];
#pragma unroll
        for (int j = 0; j < 4; j++) {
            int col = n0 + wn * 32 + j * 8 + (lane & 3) * 2;
            if (tA >= 0) {
                float* p = out + (size_t)tA * HDIM + col;
                atomicAdd(p + 0, acc[mb][j][0] * wA);
                atomicAdd(p + 1, acc[mb][j][1] * wA);
            }
            if (tB >= 0) {
                float* p = out + (size_t)tB * HDIM + col;
                atomicAdd(p + 0, acc[mb][j][2] * wB);
                atomicAdd(p + 1, acc[mb][j][3] * wB);
            }
        }
    }
}

// ---------------- launcher ----------------
extern "C" void kernel_launch(void* const* d_in, const int* in_sizes, int n_in,
                              void* d_out, int out_size) {
    const float* x      = (const float*)d_in[0];
    const float* gate_w = (const float*)d_in[1];
    const float* w1     = (const float*)d_in[2];
    const float* w2     = (const float*)d_in[3];
    const float* w3     = (const float*)d_in[4];
    float* out          = (float*)d_out;
    float* logits_out   = out + (size_t)OUT_ELEMS;
    (void)in_sizes; (void)n_in; (void)out_size;

    const int smem1 = G1_STAGES * G1_STAGEB;   // 65536
    const int smem2 = G2_STAGES * G2_STAGEB;   // 49152
    cudaFuncSetAttribute(gemm1_mma, cudaFuncAttributeMaxDynamicSharedMemorySize, smem1);
    cudaFuncSetAttribute(gemm2_mma, cudaFuncAttributeMaxDynamicSharedMemorySize, smem2);

    init_kernel<<<(OUT_ELEMS + 255) / 256, 256>>>(out);
    router_kernel<<<T_TOK / 8, 256>>>(x, gate_w, logits_out);
    scan_kernel<<<1, 1>>>();
    scatter_kernel<<<(T_TOK + 255) / 256, 256>>>();

    dim3 g1(ROWS_MAX / BM, FDIM / 64);
    gemm1_mma<<<g1, 128, smem1>>>(w1, w3);
    dim3 g2(ROWS_MAX / BM, HDIM / 64);
    gemm2_mma<<<g2, 128, smem2>>>(w2, out);
}